// round 2
// baseline (speedup 1.0000x reference)
#include <cuda_runtime.h>
#include <cstdint>

#define NPRI   32768
#define BIMG   128
#define TOPK   400
#define KEEPK  200
#define NMS_T  0.5f
#define CONF_T 0.5f
#define WORDS  13          // ceil(400/32)
#define NTH    1024

struct SM {
    unsigned keys[NPRI];              // 131072 B : score bits (0 = invalid)
    unsigned hist[2048];              //   8192 B
    unsigned long long sortbuf[512];  //   4096 B
    unsigned gt_idx[TOPK];            //   1600 B
    unsigned eq_idx[512];             //   2048 B
    float cb0[TOPK], cb1[TOPK], cb2[TOPK], cb3[TOPK];   // 6400 B
    float carea[TOPK];                //   1600 B
    float cscore[TOPK];               //   1600 B
    int   clabel[TOPK];               //   1600 B
    unsigned M[TOPK][WORDS];          //  20800 B suppression bitmatrix
    unsigned keepw[WORDS];            //     52 B
    int gsum[64];                     //    256 B
    unsigned prefix;
    int need;
    unsigned cnt_gt, cnt_eq;
    int ksel;
};

// Bitonic sort of 512 u64 keys in smem. asc=true -> ascending.
__device__ void bitonic512(unsigned long long* a, bool asc) {
    const int tid = threadIdx.x;
    for (unsigned k = 2; k <= 512; k <<= 1) {
        for (unsigned j = k >> 1; j > 0; j >>= 1) {
            __syncthreads();
            for (unsigned i = tid; i < 512; i += NTH) {
                unsigned ixj = i ^ j;
                if (ixj > i) {
                    unsigned long long x = a[i], y = a[ixj];
                    bool up = (((i & k) == 0) == asc);
                    bool swap = up ? (x > y) : (x < y);
                    if (swap) { a[i] = y; a[ixj] = x; }
                }
            }
        }
    }
    __syncthreads();
}

__global__ void __launch_bounds__(NTH, 1)
boxsel_kernel(const float* __restrict__ pred_all,
              const float* __restrict__ priors,
              float* __restrict__ out) {
    extern __shared__ unsigned char smraw[];
    SM* s = reinterpret_cast<SM*>(smraw);

    const int tid  = threadIdx.x;
    const int lane = tid & 31;
    const int wid  = tid >> 5;
    const int b    = blockIdx.x;
    const float* pred = pred_all + (size_t)b * NPRI * 6;

    // ---------------- Phase 1: scores -> key bits ----------------
    for (int i = tid; i < NPRI; i += NTH) {
        const float2 cc = *reinterpret_cast<const float2*>(pred + (size_t)i * 6 + 4);
        float sc = fmaxf(cc.x, cc.y);
        s->keys[i] = (sc > CONF_T) ? __float_as_uint(sc) : 0u;
    }
    if (tid == 0) { s->prefix = 0u; s->need = TOPK; s->cnt_gt = 0u; s->cnt_eq = 0u; }
    __syncthreads();

    // ---------------- Phase 2: radix select the 400th largest key ----------------
    const unsigned shifts[3]  = {21u, 10u, 0u};
    const unsigned nbinsA[3]  = {2048u, 2048u, 1024u};
    const unsigned pmasks[3]  = {0u, 0xFFE00000u, 0xFFFFFC00u};

    for (int p = 0; p < 3; p++) {
        const unsigned nb = nbinsA[p], sh = shifts[p], pm = pmasks[p];
        const unsigned pref = s->prefix;
        for (int i = tid; i < (int)nb; i += NTH) s->hist[i] = 0u;
        __syncthreads();

        for (int i = tid; i < NPRI; i += NTH) {
            unsigned k = s->keys[i];
            bool ok = ((k & pm) == pref);
            int bin = ok ? (int)((k >> sh) & (nb - 1u)) : (int)(nb + lane);
            unsigned grp = __match_any_sync(0xFFFFFFFFu, bin);
            int leader = __ffs(grp) - 1;
            if (lane == leader && ok) atomicAdd(&s->hist[bin], __popc(grp));
        }
        __syncthreads();

        const int ng = (int)(nb >> 5);
        if (tid < ng) {
            unsigned ssum = 0;
            #pragma unroll 8
            for (int j2 = 0; j2 < 32; j2++) ssum += s->hist[tid * 32 + j2];
            s->gsum[tid] = (int)ssum;
        }
        __syncthreads();
        if (tid == 0) {
            int need = s->need;
            int g = ng - 1;
            for (; g > 0; --g) {
                if (s->gsum[g] >= need) break;
                need -= s->gsum[g];
            }
            int bin = g * 32 + 31;
            for (; bin > g * 32; --bin) {
                if ((int)s->hist[bin] >= need) break;
                need -= (int)s->hist[bin];
            }
            s->prefix = pref | ((unsigned)bin << sh);
            s->need = need;
        }
        __syncthreads();
    }

    const unsigned kth = s->prefix;
    int need = (kth == 0u) ? 0 : s->need;   // kth==0 -> fewer than 400 valid

    // ---------------- Phase 3: compaction ----------------
    for (int i = tid; i < NPRI; i += NTH) {
        unsigned k = s->keys[i];
        if (k > kth) {
            unsigned p2 = atomicAdd(&s->cnt_gt, 1u);
            if (p2 < TOPK) s->gt_idx[p2] = (unsigned)i;
        } else if (kth != 0u && k == kth) {
            unsigned p2 = atomicAdd(&s->cnt_eq, 1u);
            if (p2 < 512u) s->eq_idx[p2] = (unsigned)i;
        }
    }
    __syncthreads();

    const int cg = min((int)s->cnt_gt, TOPK);
    const int ce = min((int)s->cnt_eq, 512);
    const int take = min(need, ce);

    // sort equal-to-kth indices ascending, take the `take` smallest (top_k stability)
    for (int t = tid; t < 512; t += NTH)
        s->sortbuf[t] = (t < ce) ? (unsigned long long)s->eq_idx[t] : ~0ull;
    bitonic512(s->sortbuf, true);
    if (tid < take) s->gt_idx[cg + tid] = (unsigned)s->sortbuf[tid];
    __syncthreads();

    const int ksel = cg + take;

    // ---------------- Phase 4: sort candidates (score desc, idx asc) ----------------
    for (int t = tid; t < 512; t += NTH) {
        if (t < ksel) {
            unsigned idx = s->gt_idx[t];
            s->sortbuf[t] = ((unsigned long long)s->keys[idx] << 32) | (unsigned)(~idx);
        } else {
            s->sortbuf[t] = 0ull;
        }
    }
    bitonic512(s->sortbuf, false);   // descending

    // ---------------- Phase 5: decode candidate boxes ----------------
    for (int t = tid; t < TOPK; t += NTH) {
        if (t < ksel) {
            unsigned long long key = s->sortbuf[t];
            unsigned idx = ~((unsigned)key);
            const float* pp = pred + (size_t)idx * 6;
            float l0 = pp[0], l1 = pp[1], l2 = pp[2], l3 = pp[3];
            float c0 = pp[4], c1 = pp[5];
            const float* qq = priors + (size_t)idx * 4;
            float p0 = qq[0], p1 = qq[1], p2 = qq[2], p3 = qq[3];
            float cx = p0 + l0 * 0.1f * p2;
            float cy = p1 + l1 * 0.1f * p3;
            float w  = p2 * expf(l2 * 0.2f);
            float h  = p3 * expf(l3 * 0.2f);
            float x1 = cx - w * 0.5f, y1 = cy - h * 0.5f;
            float x2 = cx + w * 0.5f, y2 = cy + h * 0.5f;
            s->cb0[t] = x1; s->cb1[t] = y1; s->cb2[t] = x2; s->cb3[t] = y2;
            s->carea[t]  = (x2 - x1) * (y2 - y1);
            s->cscore[t] = __uint_as_float((unsigned)(key >> 32));
            s->clabel[t] = (c1 > c0) ? 1 : 0;
        } else {
            s->cb0[t] = 0.f; s->cb1[t] = 0.f; s->cb2[t] = 0.f; s->cb3[t] = 0.f;
            s->carea[t] = 0.f; s->cscore[t] = -1e30f; s->clabel[t] = 0;
        }
    }
    __syncthreads();

    // keep-mask init (valid = score > CONF_T), 13 full warps participate
    if (tid < WORDS * 32) {
        bool v = (tid < TOPK) && (s->cscore[tid] > CONF_T);
        unsigned wd = __ballot_sync(0xFFFFFFFFu, v);
        if (lane == 0) s->keepw[wid] = wd;
    }

    // ---------------- Phase 6: suppression bit-matrix (fully parallel) ----------------
    for (int task = wid; task < TOPK * WORDS; task += 32) {
        int r = task / WORDS;
        int w = task - r * WORDS;
        int j = w * 32 + lane;
        bool sup = false;
        if (j > r && j < TOPK) {
            float iw = fminf(s->cb2[r], s->cb2[j]) - fmaxf(s->cb0[r], s->cb0[j]);
            float ih = fminf(s->cb3[r], s->cb3[j]) - fmaxf(s->cb1[r], s->cb1[j]);
            iw = fmaxf(iw, 0.f); ih = fmaxf(ih, 0.f);
            float inter = iw * ih;
            float iou = inter / (s->carea[r] + s->carea[j] - inter + 1e-12f);
            sup = (iou > NMS_T);
        }
        unsigned word = __ballot_sync(0xFFFFFFFFu, sup);
        if (lane == 0) s->M[r][w] = word;
    }
    __syncthreads();

    // ---------------- Phase 7: sequential NMS scan (single warp) ----------------
    if (wid == 0) {
        unsigned kw = (lane < WORDS) ? s->keepw[lane] : 0u;
        unsigned mrow_next = (lane < WORDS) ? s->M[0][lane] : 0u;
        for (int i = 0; i < TOPK; i++) {
            unsigned mrow = mrow_next;
            if (i + 1 < TOPK)
                mrow_next = (lane < WORDS) ? s->M[i + 1][lane] : 0u;
            unsigned dw = __shfl_sync(0xFFFFFFFFu, kw, i >> 5);
            if ((dw >> (i & 31)) & 1u)
                kw &= ~mrow;
        }
        if (lane < WORDS) s->keepw[lane] = kw;
    }
    __syncthreads();

    // ---------------- Phase 8: stable ascending sort of kept, emit 200 rows ----------------
    for (int t = tid; t < 512; t += NTH) {
        bool kept = (t < TOPK) && ((s->keepw[t >> 5] >> (t & 31)) & 1u);
        s->sortbuf[t] = kept
            ? (((unsigned long long)__float_as_uint(s->cscore[t]) << 32) | (unsigned)t)
            : ~0ull;
    }
    bitonic512(s->sortbuf, true);   // ascending; sentinels sink to the end

    for (int r = tid; r < KEEPK; r += NTH) {
        unsigned long long key = s->sortbuf[r];
        float* o = out + ((size_t)b * KEEPK + r) * 6;
        if ((unsigned)(key >> 32) != 0xFFFFFFFFu) {
            unsigned t = (unsigned)key;
            o[0] = (float)s->clabel[t];
            o[1] = s->cscore[t];
            o[2] = s->cb0[t];
            o[3] = s->cb1[t];
            o[4] = s->cb2[t];
            o[5] = s->cb3[t];
        } else {
            o[0] = 0.f; o[1] = 0.f; o[2] = 0.f; o[3] = 0.f; o[4] = 0.f; o[5] = 0.f;
        }
    }
}

extern "C" void kernel_launch(void* const* d_in, const int* in_sizes, int n_in,
                              void* d_out, int out_size) {
    const float* pred   = (const float*)d_in[0];
    const float* priors = (const float*)d_in[1];
    float* out = (float*)d_out;

    cudaFuncSetAttribute(boxsel_kernel,
                         cudaFuncAttributeMaxDynamicSharedMemorySize,
                         (int)sizeof(SM));
    boxsel_kernel<<<BIMG, NTH, sizeof(SM)>>>(pred, priors, out);
}

// round 4
// speedup vs baseline: 1.8962x; 1.8962x over previous
#include <cuda_runtime.h>
#include <cstdint>

#define NPRI   32768
#define BIMG   128
#define TOPK   400
#define KEEPK  200
#define NMS_T  0.5f
#define CONF_T 0.5f
#define WORDS  13          // ceil(400/32)
#define NTH    1024
#define FULLM  0xFFFFFFFFu

struct SM {
    unsigned keys[NPRI];              // 131072 B : score bits (0 = invalid)
    unsigned hist[2048];              //   8192 B
    unsigned long long sortbuf[512];  //   4096 B
    unsigned gt_idx[512];             //   2048 B
    unsigned eq_idx[2048];            //   8192 B
    float cb0[TOPK], cb1[TOPK], cb2[TOPK], cb3[TOPK];   // 6400 B
    float carea[TOPK];                //   1600 B
    float cscore[TOPK];               //   1600 B
    int   clabel[TOPK];               //   1600 B
    unsigned M[TOPK][WORDS];          //  20800 B suppression bitmatrix
    unsigned keepw[WORDS];
    int gsum[64];
    unsigned prefix;
    int need;
    unsigned cnt_gt, cnt_eq;
};

// 512-element bitonic sort; threads 0..511 carry one u64 in a register.
// All NTH threads must call (barrier participation). Returns sorted value
// for position t (t<512).
__device__ __forceinline__ unsigned long long
sort512(unsigned long long v, bool asc, unsigned long long* buf) {
    const int t = threadIdx.x;
    const bool act = t < 512;
    #pragma unroll
    for (unsigned k = 2; k <= 512; k <<= 1) {
        // smem stages: j = k/2 .. 32
        #pragma unroll
        for (unsigned j = k >> 1; j >= 32; j >>= 1) {
            if (act) buf[t] = v;
            __syncthreads();
            if (act) {
                unsigned long long o = buf[t ^ j];
                bool up = (((t & k) == 0) == asc);
                bool hi = (t & j) != 0;
                v = ((hi == up) ? (v > o) : (v < o)) ? v : o;
            }
            __syncthreads();
        }
        // shfl stages: j = min(k/2,16) .. 1
        unsigned jstart = ((k >> 1) > 16u) ? 16u : (k >> 1);
        #pragma unroll
        for (unsigned j = 16; j >= 1; j >>= 1) {
            if (j > jstart) continue;
            if (act) {
                unsigned long long o = __shfl_xor_sync(FULLM, v, j);
                bool up = (((t & k) == 0) == asc);
                bool hi = (t & j) != 0;
                v = ((hi == up) ? (v > o) : (v < o)) ? v : o;
            }
        }
    }
    return v;
}

// Scan histogram (nb bins) downward for s->need-th largest; updates prefix/need.
__device__ __forceinline__ void select_bin(SM* s, unsigned nb, unsigned sh) {
    const int tid = threadIdx.x;
    const int ng = (int)(nb >> 5);
    if (tid < ng) {
        unsigned ssum = 0;
        #pragma unroll 8
        for (int j = 0; j < 32; j++) ssum += s->hist[tid * 32 + j];
        s->gsum[tid] = (int)ssum;
    }
    __syncthreads();
    if (tid == 0) {
        int need = s->need;
        int g = ng - 1;
        for (; g > 0; --g) {
            if (s->gsum[g] >= need) break;
            need -= s->gsum[g];
        }
        int bin = g * 32 + 31;
        for (; bin > g * 32; --bin) {
            if ((int)s->hist[bin] >= need) break;
            need -= (int)s->hist[bin];
        }
        s->prefix |= ((unsigned)bin << sh);
        s->need = need;
    }
    __syncthreads();
}

__global__ void __launch_bounds__(NTH, 1)
boxsel_kernel(const float* __restrict__ pred_all,
              const float* __restrict__ priors,
              float* __restrict__ out) {
    extern __shared__ unsigned char smraw[];
    SM* s = reinterpret_cast<SM*>(smraw);

    const int tid  = threadIdx.x;
    const int lane = tid & 31;
    const int wid  = tid >> 5;
    const int b    = blockIdx.x;
    const float* pred = pred_all + (size_t)b * NPRI * 6;

    // ---------------- Phase 1: coalesced load, keys + fused pass-1 histogram ----------------
    for (int i = tid; i < 2048; i += NTH) s->hist[i] = 0u;
    if (tid == 0) { s->prefix = 0u; s->need = TOPK; s->cnt_gt = 0u; s->cnt_eq = 0u; }
    __syncthreads();

    {
        const float4* p4 = reinterpret_cast<const float4*>(pred);
        #pragma unroll
        for (int it = 0; it < NPRI / (4 * NTH); it++) {   // 8 iterations
            int g = tid + it * NTH;                        // group of 4 priors
            float4 a = p4[6 * g + 1];   // confs of prior 0 at .x,.y
            float4 bq = p4[6 * g + 2];  // confs of prior 1 at .z,.w
            float4 c = p4[6 * g + 4];   // confs of prior 2 at .x,.y
            float4 d = p4[6 * g + 5];   // confs of prior 3 at .z,.w
            float sc0 = fmaxf(a.x, a.y);
            float sc1 = fmaxf(bq.z, bq.w);
            float sc2 = fmaxf(c.x, c.y);
            float sc3 = fmaxf(d.z, d.w);
            unsigned kk[4];
            kk[0] = (sc0 > CONF_T) ? __float_as_uint(sc0) : 0u;
            kk[1] = (sc1 > CONF_T) ? __float_as_uint(sc1) : 0u;
            kk[2] = (sc2 > CONF_T) ? __float_as_uint(sc2) : 0u;
            kk[3] = (sc3 > CONF_T) ? __float_as_uint(sc3) : 0u;
            *reinterpret_cast<uint4*>(&s->keys[4 * g]) =
                make_uint4(kk[0], kk[1], kk[2], kk[3]);
            #pragma unroll
            for (int q = 0; q < 4; q++) {
                bool nz = kk[q] != 0u;
                unsigned m = __ballot_sync(FULLM, nz);
                if (nz) {
                    int bin = (int)(kk[q] >> 21);
                    unsigned grp = __match_any_sync(m, bin);
                    if (lane == __ffs(grp) - 1)
                        atomicAdd(&s->hist[bin], __popc(grp));
                }
            }
        }
    }
    __syncthreads();

    // ---------------- Phase 2: radix select the 400th largest key ----------------
    select_bin(s, 2048u, 21u);     // pass 1 (histogram was fused above)

    const unsigned shifts[3] = {21u, 10u, 0u};
    const unsigned nbinsA[3] = {2048u, 2048u, 1024u};
    const unsigned pmasks[3] = {0u, 0xFFE00000u, 0xFFFFFC00u};

    for (int p = 1; p < 3; p++) {
        const unsigned nb = nbinsA[p], sh = shifts[p], pm = pmasks[p];
        const unsigned pref = s->prefix;
        for (int i = tid; i < (int)nb; i += NTH) s->hist[i] = 0u;
        __syncthreads();

        #pragma unroll 4
        for (int i = tid; i < NPRI; i += NTH) {
            unsigned k = s->keys[i];
            bool ok = ((k & pm) == pref);
            unsigned m = __ballot_sync(FULLM, ok);
            if (ok) {
                int bin = (int)((k >> sh) & (nb - 1u));
                unsigned grp = __match_any_sync(m, bin);
                if (lane == __ffs(grp) - 1)
                    atomicAdd(&s->hist[bin], __popc(grp));
            }
        }
        __syncthreads();
        select_bin(s, nb, sh);
    }

    const unsigned kth = s->prefix;
    const int need = (kth == 0u) ? 0 : s->need;   // kth==0 -> fewer than 400 valid

    // ---------------- Phase 3: compaction ----------------
    #pragma unroll 4
    for (int i = tid; i < NPRI; i += NTH) {
        unsigned k = s->keys[i];
        if (k > kth) {
            unsigned p2 = atomicAdd(&s->cnt_gt, 1u);
            if (p2 < 512u) s->gt_idx[p2] = (unsigned)i;
        } else if (kth != 0u && k == kth) {
            unsigned p2 = atomicAdd(&s->cnt_eq, 1u);
            if (p2 < 2048u) s->eq_idx[p2] = (unsigned)i;
        }
    }
    __syncthreads();

    const int cg   = min((int)s->cnt_gt, TOPK);   // radix guarantees < 400
    const int ce   = min((int)s->cnt_eq, 2048);
    const int take = min(need, ce);
    int cn;                                        // candidates entering the sort

    if (cg + ce <= 512) {
        // common path: throw ALL eq into the (score desc, idx asc) sort;
        // truncation to ksel = cg+take keeps exactly the smallest-index ties.
        for (int e = tid; e < ce; e += NTH) s->gt_idx[cg + e] = s->eq_idx[e];
        cn = cg + ce;
    } else {
        // rare path: rank-select the `take` smallest eq indices.
        for (int e = tid; e < ce; e += NTH) {
            unsigned my = s->eq_idx[e];
            int r = 0;
            for (int q = 0; q < ce; q++) r += (s->eq_idx[q] < my);
            if (r < take) s->gt_idx[cg + r] = my;
        }
        cn = cg + take;
    }
    __syncthreads();

    const int ksel = cg + take;

    // ---------------- Phase 4: sort candidates (score desc, idx asc) ----------------
    {
        unsigned long long v = 0ull;
        if (tid < cn) {
            unsigned idx = s->gt_idx[tid];
            v = ((unsigned long long)s->keys[idx] << 32) | (unsigned)(~idx);
        }
        v = sort512(v, false, s->sortbuf);          // descending
        if (tid < 512) s->sortbuf[tid] = v;
        __syncthreads();
    }

    // ---------------- Phase 5: decode candidate boxes ----------------
    if (tid < TOPK) {
        const int t = tid;
        if (t < ksel) {
            unsigned long long key = s->sortbuf[t];
            unsigned idx = ~((unsigned)key);
            const float* pp = pred + (size_t)idx * 6;
            float l0 = pp[0], l1 = pp[1], l2 = pp[2], l3 = pp[3];
            float c0 = pp[4], c1 = pp[5];
            const float* qq = priors + (size_t)idx * 4;
            float p0 = qq[0], p1 = qq[1], p2 = qq[2], p3 = qq[3];
            float cx = p0 + l0 * 0.1f * p2;
            float cy = p1 + l1 * 0.1f * p3;
            float w  = p2 * expf(l2 * 0.2f);
            float h  = p3 * expf(l3 * 0.2f);
            float x1 = cx - w * 0.5f, y1 = cy - h * 0.5f;
            float x2 = cx + w * 0.5f, y2 = cy + h * 0.5f;
            s->cb0[t] = x1; s->cb1[t] = y1; s->cb2[t] = x2; s->cb3[t] = y2;
            s->carea[t]  = (x2 - x1) * (y2 - y1);
            s->cscore[t] = __uint_as_float((unsigned)(key >> 32));
            s->clabel[t] = (c1 > c0) ? 1 : 0;
        } else {
            s->cb0[t] = 0.f; s->cb1[t] = 0.f; s->cb2[t] = 0.f; s->cb3[t] = 0.f;
            s->carea[t] = 0.f; s->cscore[t] = -1e30f; s->clabel[t] = 0;
        }
    }
    __syncthreads();

    // keep-mask init (valid = score > CONF_T)
    if (tid < WORDS * 32) {
        bool v = (tid < TOPK) && (s->cscore[tid] > CONF_T);
        unsigned wd = __ballot_sync(FULLM, v);
        if (lane == 0) s->keepw[wid] = wd;
    }

    // ---------------- Phase 6: suppression bit-matrix (row per warp) ----------------
    for (int r = wid; r < TOPK; r += 32) {
        float rb0 = s->cb0[r], rb1 = s->cb1[r];
        float rb2 = s->cb2[r], rb3 = s->cb3[r];
        float ra  = s->carea[r];
        #pragma unroll
        for (int w = 0; w < WORDS; w++) {
            if (w * 32 + 31 <= r) {                // whole word in lower triangle
                if (lane == 0) s->M[r][w] = 0u;
                continue;
            }
            int j = w * 32 + lane;
            bool sup = false;
            if (j > r && j < TOPK) {
                float iw = fminf(rb2, s->cb2[j]) - fmaxf(rb0, s->cb0[j]);
                float ih = fminf(rb3, s->cb3[j]) - fmaxf(rb1, s->cb1[j]);
                iw = fmaxf(iw, 0.f); ih = fmaxf(ih, 0.f);
                float inter = iw * ih;
                float iou = inter / (ra + s->carea[j] - inter + 1e-12f);
                sup = (iou > NMS_T);
            }
            unsigned word = __ballot_sync(FULLM, sup);
            if (lane == 0) s->M[r][w] = word;
        }
    }
    __syncthreads();

    // ---------------- Phase 7: sequential NMS scan (single warp) ----------------
    if (wid == 0) {
        unsigned kw = (lane < WORDS) ? s->keepw[lane] : 0u;
        unsigned mrow_next = (lane < WORDS) ? s->M[0][lane] : 0u;
        for (int i = 0; i < TOPK; i++) {
            unsigned mrow = mrow_next;
            if (i + 1 < TOPK)
                mrow_next = (lane < WORDS) ? s->M[i + 1][lane] : 0u;
            unsigned dw = __shfl_sync(FULLM, kw, i >> 5);
            if ((dw >> (i & 31)) & 1u)
                kw &= ~mrow;
        }
        if (lane < WORDS) s->keepw[lane] = kw;
    }
    __syncthreads();

    // ---------------- Phase 8: stable ascending sort of kept, emit 200 rows ----------------
    {
        unsigned long long v = ~0ull;
        if (tid < TOPK) {
            bool kept = (s->keepw[tid >> 5] >> (tid & 31)) & 1u;
            if (kept)
                v = (((unsigned long long)__float_as_uint(s->cscore[tid]) << 32)
                     | (unsigned)tid);
        }
        v = sort512(v, true, s->sortbuf);            // ascending; sentinels sink
        if (tid < 512) s->sortbuf[tid] = v;
        __syncthreads();
    }

    if (tid < KEEPK) {
        unsigned long long key = s->sortbuf[tid];
        float* o = out + ((size_t)b * KEEPK + tid) * 6;
        if ((unsigned)(key >> 32) != 0xFFFFFFFFu) {
            unsigned t = (unsigned)key;
            o[0] = (float)s->clabel[t];
            o[1] = s->cscore[t];
            o[2] = s->cb0[t];
            o[3] = s->cb1[t];
            o[4] = s->cb2[t];
            o[5] = s->cb3[t];
        } else {
            o[0] = 0.f; o[1] = 0.f; o[2] = 0.f; o[3] = 0.f; o[4] = 0.f; o[5] = 0.f;
        }
    }
}

extern "C" void kernel_launch(void* const* d_in, const int* in_sizes, int n_in,
                              void* d_out, int out_size) {
    const float* pred   = (const float*)d_in[0];
    const float* priors = (const float*)d_in[1];
    float* out = (float*)d_out;

    cudaFuncSetAttribute(boxsel_kernel,
                         cudaFuncAttributeMaxDynamicSharedMemorySize,
                         (int)sizeof(SM));
    boxsel_kernel<<<BIMG, NTH, sizeof(SM)>>>(pred, priors, out);
}